// round 15
// baseline (speedup 1.0000x reference)
#include <cuda_runtime.h>
#include <cstdint>
#include <math.h>

// Problem constants
#define BH 64
#define NSEQ 4096
#define DHEAD 64
#define MFEAT 256
#define RATIO 0.0625f             // 256^-0.5
#define KEPS 1e-4f
#define CH 16                     // row-chunks for k12 (256 rows each)
#define STAGES 8                  // 256/32 rows per stage

// log2-domain constants
#define DN_L2E   0.510069723f     // 64^-0.25 * log2(e)
#define HDN2_L2E 0.0901684401f    // 0.5 * 64^-0.5 * log2(e)

typedef unsigned long long u64;

// MUFU exp2 (guaranteed EX2.APPROX)
__device__ __forceinline__ float ex2f(float x) {
    float y; asm("ex2.approx.f32 %0, %1;" : "=f"(y) : "f"(x)); return y;
}

// Packed fp32x2 helpers
__device__ __forceinline__ u64 ffma2(u64 a, u64 b, u64 c) {
    u64 d;
    asm("fma.rn.f32x2 %0, %1, %2, %3;" : "=l"(d) : "l"(a), "l"(b), "l"(c));
    return d;
}
__device__ __forceinline__ u64 fmul2(u64 a, u64 b) {
    u64 d;
    asm("mul.rn.f32x2 %0, %1, %2;" : "=l"(d) : "l"(a), "l"(b));
    return d;
}
__device__ __forceinline__ u64 fadd2(u64 a, u64 b) {
    u64 d;
    asm("add.rn.f32x2 %0, %1, %2;" : "=l"(d) : "l"(a), "l"(b));
    return d;
}
__device__ __forceinline__ u64 pack2(float lo, float hi) {
    u64 d; asm("mov.b64 %0, {%1, %2};" : "=l"(d) : "f"(lo), "f"(hi)); return d;
}
__device__ __forceinline__ float2 unpack2(u64 v) {
    float lo, hi; asm("mov.b64 {%0, %1}, %2;" : "=f"(lo), "=f"(hi) : "l"(v));
    return make_float2(lo, hi);
}

// Packed exp2 on the FMA pipe (degree-5 poly, rel err ~2e-6).
__device__ __forceinline__ u64 exp2_poly2(float y0, float y1) {
    y0 = fmaxf(y0, -120.f);
    y1 = fmaxf(y1, -120.f);
    u64 y = pack2(y0, y1);
    const u64 C  = pack2(12582912.f, 12582912.f);    // 1.5*2^23
    const u64 nC = pack2(-12582912.f, -12582912.f);
    const u64 n1 = pack2(-1.f, -1.f);
    u64 z  = fadd2(y, C);
    u64 iz = fadd2(z, nC);
    u64 f  = ffma2(iz, n1, y);
    u64 p  = pack2(0.00133335581f, 0.00133335581f);
    p = ffma2(p, f, pack2(0.00961812911f, 0.00961812911f));
    p = ffma2(p, f, pack2(0.05550410866f, 0.05550410866f));
    p = ffma2(p, f, pack2(0.24022650696f, 0.24022650696f));
    p = ffma2(p, f, pack2(0.69314718056f, 0.69314718056f));
    p = ffma2(p, f, pack2(1.f, 1.f));
    uint32_t zlo, zhi;
    asm("mov.b64 {%0,%1}, %2;" : "=r"(zlo), "=r"(zhi) : "l"(z));
    uint32_t slo = zlo * 8388608u + 0x3F800000u;
    uint32_t shi = zhi * 8388608u + 0x3F800000u;
    u64 s; asm("mov.b64 %0, {%1,%2};" : "=l"(s) : "r"(slo), "r"(shi));
    return fmul2(p, s);
}

// cp.async helpers
__device__ __forceinline__ void cp_async16(uint32_t s, const void* g) {
    asm volatile("cp.async.cg.shared.global [%0], [%1], 16;" :: "r"(s), "l"(g));
}
__device__ __forceinline__ void cp_commit() {
    asm volatile("cp.async.commit_group;" ::: "memory");
}
__device__ __forceinline__ void cp_wait0() {
    asm volatile("cp.async.wait_group 0;" ::: "memory");
}
template<int N> __device__ __forceinline__ void cp_wait() {
    asm volatile("cp.async.wait_group %0;" :: "n"(N) : "memory");
}

// Scratch (device globals). All entries fully rewritten each call.
__device__ float g_ctx_part[(size_t)BH * CH * MFEAT * DHEAD]; // 67 MB
__device__ float g_ksum_part[BH * CH * MFEAT];
__device__ float g_lmax[BH * CH * 2];     // log2-domain
__device__ float g_scale[BH * CH * 2];
__device__ float g_vsum[BH * DHEAD];
__device__ float g_ctx[(size_t)BH * MFEAT * DHEAD];           // 4 MB
__device__ float g_ksum[BH * MFEAT];

// ---------------------------------------------------------------------------
// k12: fused K-features + partial ctx/ksum (unchanged, passing).
// ---------------------------------------------------------------------------
#define K12_SMEM 84480

__global__ __launch_bounds__(256, 2) void k12_ctx(const float* __restrict__ K,
                                                  const float* __restrict__ V,
                                                  const float* __restrict__ P) {
    extern __shared__ __align__(16) char smraw[];
    float* Pt  = (float*)smraw;                    // [64][132]
    float* Ks  = (float*)(smraw + 33792);          // [2][32][68]
    float* Vs  = (float*)(smraw + 51200);          // [2][32][64]
    float* kps = (float*)(smraw + 67584);          // [32][132]
    __shared__ float wmax[8];

    const int bh = blockIdx.y;
    const int chunk = blockIdx.x >> 1;
    const int fh = blockIdx.x & 1;
    const int fbase = fh * 128;
    const int t = threadIdx.x;
    const int w = t >> 5, lane = t & 31;
    const int fgrp = (w & 3) * 32 + (lane & 7) * 4;
    const int egrp = (w >> 2) * 32 + (lane >> 3) * 8;

    const float* kb = K + ((size_t)bh * NSEQ + (size_t)chunk * 256) * 64;
    const float* vb = V + ((size_t)bh * NSEQ + (size_t)chunk * 256) * 64;

    uint32_t ks_s = (uint32_t)__cvta_generic_to_shared(Ks);
    uint32_t vs_s = (uint32_t)__cvta_generic_to_shared(Vs);

    {
        int c0 = t, c1 = t + 256;
        int r0 = c0 >> 4, q0 = c0 & 15, r1 = c1 >> 4, q1 = c1 & 15;
        cp_async16(ks_s + r0 * 272 + q0 * 16, kb + r0 * 64 + q0 * 4);
        cp_async16(ks_s + r1 * 272 + q1 * 16, kb + r1 * 64 + q1 * 4);
        cp_async16(vs_s + r0 * 256 + q0 * 16, vb + r0 * 64 + q0 * 4);
        cp_async16(vs_s + r1 * 256 + q1 * 16, vb + r1 * 64 + q1 * 4);
        cp_commit();
    }

    for (int idx = t; idx < 128 * 64; idx += 256) {
        int f = idx >> 6, d = idx & 63;
        Pt[d * 132 + f] = DN_L2E * P[(size_t)(fbase + f) * 64 + d];
    }

    u64 ctx2[16];
    #pragma unroll
    for (int i = 0; i < 16; i++) ctx2[i] = 0ull;
    float ks0 = 0.f, ks1 = 0.f, ks2 = 0.f, ks3 = 0.f;
    float M = -1e30f;

    for (int st = 0; st < STAGES; st++) {
        const int buf = st & 1;
        cp_wait0();
        __syncthreads();

        if (st + 1 < STAGES) {
            const float* kn = kb + (st + 1) * 32 * 64;
            const float* vn = vb + (st + 1) * 32 * 64;
            uint32_t kd = ks_s + (buf ^ 1) * 8704;
            uint32_t vd = vs_s + (buf ^ 1) * 8192;
            int c0 = t, c1 = t + 256;
            int r0 = c0 >> 4, q0 = c0 & 15, r1 = c1 >> 4, q1 = c1 & 15;
            cp_async16(kd + r0 * 272 + q0 * 16, kn + r0 * 64 + q0 * 4);
            cp_async16(kd + r1 * 272 + q1 * 16, kn + r1 * 64 + q1 * 4);
            cp_async16(vd + r0 * 256 + q0 * 16, vn + r0 * 64 + q0 * 4);
            cp_async16(vd + r1 * 256 + q1 * 16, vn + r1 * 64 + q1 * 4);
            cp_commit();
        }

        const float* ksb = Ks + buf * 2176;
        const float* vsb = Vs + buf * 2048;

        float diag_r[4];
        #pragma unroll
        for (int i = 0; i < 4; i++) {
            const float* kr = ksb + (w * 4 + i) * 68;
            float2 v2 = *(const float2*)(kr + 2 * lane);
            float ss = v2.x * v2.x + v2.y * v2.y;
            #pragma unroll
            for (int o = 16; o; o >>= 1) ss += __shfl_xor_sync(0xffffffffu, ss, o);
            diag_r[i] = HDN2_L2E * ss;
        }

        u64 acc[4][2];
        #pragma unroll
        for (int i = 0; i < 4; i++) { acc[i][0] = 0ull; acc[i][1] = 0ull; }
        const float* kr0 = ksb + (w * 4 + 0) * 68;
        const float* kr1 = ksb + (w * 4 + 1) * 68;
        const float* kr2 = ksb + (w * 4 + 2) * 68;
        const float* kr3 = ksb + (w * 4 + 3) * 68;
        #pragma unroll 4
        for (int d = 0; d < 64; d += 4) {
            float4 k0 = *(const float4*)(kr0 + d);
            float4 k1 = *(const float4*)(kr1 + d);
            float4 k2 = *(const float4*)(kr2 + d);
            float4 k3 = *(const float4*)(kr3 + d);
            #pragma unroll
            for (int q = 0; q < 4; q++) {
                ulonglong2 pv = *(const ulonglong2*)(Pt + (d + q) * 132 + lane * 4);
                float kq0 = (q == 0) ? k0.x : (q == 1) ? k0.y : (q == 2) ? k0.z : k0.w;
                float kq1 = (q == 0) ? k1.x : (q == 1) ? k1.y : (q == 2) ? k1.z : k1.w;
                float kq2 = (q == 0) ? k2.x : (q == 1) ? k2.y : (q == 2) ? k2.z : k2.w;
                float kq3 = (q == 0) ? k3.x : (q == 1) ? k3.y : (q == 2) ? k3.z : k3.w;
                u64 b0 = pack2(kq0, kq0), b1 = pack2(kq1, kq1);
                u64 b2 = pack2(kq2, kq2), b3 = pack2(kq3, kq3);
                acc[0][0] = ffma2(b0, pv.x, acc[0][0]); acc[0][1] = ffma2(b0, pv.y, acc[0][1]);
                acc[1][0] = ffma2(b1, pv.x, acc[1][0]); acc[1][1] = ffma2(b1, pv.y, acc[1][1]);
                acc[2][0] = ffma2(b2, pv.x, acc[2][0]); acc[2][1] = ffma2(b2, pv.y, acc[2][1]);
                acc[3][0] = ffma2(b3, pv.x, acc[3][0]); acc[3][1] = ffma2(b3, pv.y, acc[3][1]);
            }
        }

        float dd[4][4];
        float mx = -1e30f;
        #pragma unroll
        for (int i = 0; i < 4; i++) {
            float2 lo = unpack2(acc[i][0]);
            float2 hi = unpack2(acc[i][1]);
            dd[i][0] = lo.x; dd[i][1] = lo.y;
            dd[i][2] = hi.x; dd[i][3] = hi.y;
            mx = fmaxf(mx, fmaxf(fmaxf(dd[i][0], dd[i][1]), fmaxf(dd[i][2], dd[i][3])));
        }
        #pragma unroll
        for (int o = 16; o; o >>= 1) mx = fmaxf(mx, __shfl_xor_sync(0xffffffffu, mx, o));
        if (lane == 0) wmax[w] = mx;
        __syncthreads();
        float smax = wmax[0];
        #pragma unroll
        for (int i = 1; i < 8; i++) smax = fmaxf(smax, wmax[i]);

        if (smax > M) {
            float sc = ex2f(M - smax);
            u64 sc2 = pack2(sc, sc);
            #pragma unroll
            for (int i = 0; i < 16; i++) ctx2[i] = fmul2(ctx2[i], sc2);
            ks0 *= sc; ks1 *= sc; ks2 *= sc; ks3 *= sc;
            M = smax;
        }

        #pragma unroll
        for (int i = 0; i < 4; i++) {
            float dmi = diag_r[i] + M;
            float k0, k1, k2v, k3v;
            if ((i & 1) == 0) {
                u64 ea = exp2_poly2(dd[i][0] - dmi, dd[i][1] - dmi);
                u64 eb = exp2_poly2(dd[i][2] - dmi, dd[i][3] - dmi);
                float2 fa = unpack2(ea), fb = unpack2(eb);
                k0 = fa.x; k1 = fa.y; k2v = fb.x; k3v = fb.y;
            } else {
                k0  = ex2f(dd[i][0] - dmi);
                k1  = ex2f(dd[i][1] - dmi);
                k2v = ex2f(dd[i][2] - dmi);
                k3v = ex2f(dd[i][3] - dmi);
            }
            ks0 += k0; ks1 += k1; ks2 += k2v; ks3 += k3v;
            *(float4*)(kps + (w * 4 + i) * 132 + lane * 4) = make_float4(k0, k1, k2v, k3v);
        }
        __syncthreads();

        #pragma unroll 4
        for (int r = 0; r < 32; r++) {
            ulonglong2 kp4 = *(const ulonglong2*)(kps + r * 132 + fgrp);
            float2 klo = unpack2(kp4.x), khi = unpack2(kp4.y);
            u64 b0 = pack2(klo.x, klo.x), b1 = pack2(klo.y, klo.y);
            u64 b2 = pack2(khi.x, khi.x), b3 = pack2(khi.y, khi.y);
            const ulonglong2* vp = (const ulonglong2*)(vsb + r * 64 + egrp);
            ulonglong2 vA = vp[0], vB = vp[1];
            ctx2[0]  = ffma2(b0, vA.x, ctx2[0]);  ctx2[1]  = ffma2(b0, vA.y, ctx2[1]);
            ctx2[2]  = ffma2(b0, vB.x, ctx2[2]);  ctx2[3]  = ffma2(b0, vB.y, ctx2[3]);
            ctx2[4]  = ffma2(b1, vA.x, ctx2[4]);  ctx2[5]  = ffma2(b1, vA.y, ctx2[5]);
            ctx2[6]  = ffma2(b1, vB.x, ctx2[6]);  ctx2[7]  = ffma2(b1, vB.y, ctx2[7]);
            ctx2[8]  = ffma2(b2, vA.x, ctx2[8]);  ctx2[9]  = ffma2(b2, vA.y, ctx2[9]);
            ctx2[10] = ffma2(b2, vB.x, ctx2[10]); ctx2[11] = ffma2(b2, vB.y, ctx2[11]);
            ctx2[12] = ffma2(b3, vA.x, ctx2[12]); ctx2[13] = ffma2(b3, vA.y, ctx2[13]);
            ctx2[14] = ffma2(b3, vB.x, ctx2[14]); ctx2[15] = ffma2(b3, vB.y, ctx2[15]);
        }
    }

    __syncthreads();

    {
        float* base = g_ctx_part + ((size_t)(bh * CH + chunk) * MFEAT) * DHEAD;
        #pragma unroll
        for (int j = 0; j < 4; j++) {
            float* op = base + (size_t)(fbase + fgrp + j) * DHEAD + egrp;
            ((ulonglong2*)op)[0] = make_ulonglong2(ctx2[j * 4 + 0], ctx2[j * 4 + 1]);
            ((ulonglong2*)op)[1] = make_ulonglong2(ctx2[j * 4 + 2], ctx2[j * 4 + 3]);
        }
    }

    *(float4*)(kps + w * 128 + lane * 4) = make_float4(ks0, ks1, ks2, ks3);
    __syncthreads();
    if (t < 128) {
        float s = 0.f;
        #pragma unroll
        for (int w2 = 0; w2 < 8; w2++) s += kps[w2 * 128 + t];
        g_ksum_part[(bh * CH + chunk) * MFEAT + fbase + t] = s;
    }
    if (t == 0) g_lmax[(bh * CH + chunk) * 2 + fh] = M;
}

// ---------------------------------------------------------------------------
// kvsum: vsum + folded kscale (unchanged).
// ---------------------------------------------------------------------------
__global__ __launch_bounds__(256) void kvsum(const float* __restrict__ V) {
    __shared__ float psum[16][64];
    const int bh = blockIdx.x, t = threadIdx.x;
    const int e4 = t & 15, rc = t >> 4;
    const float4* vb = (const float4*)V + (size_t)bh * NSEQ * 16;
    float4 acc = make_float4(0.f, 0.f, 0.f, 0.f);
    #pragma unroll 8
    for (int it = 0; it < 256; it++) {
        float4 a = vb[(size_t)(rc + 16 * it) * 16 + e4];
        acc.x += a.x; acc.y += a.y; acc.z += a.z; acc.w += a.w;
    }
    psum[rc][e4*4+0] = acc.x; psum[rc][e4*4+1] = acc.y;
    psum[rc][e4*4+2] = acc.z; psum[rc][e4*4+3] = acc.w;
    __syncthreads();
    if (t < 64) {
        float s = 0.f;
        #pragma unroll
        for (int r = 0; r < 16; r++) s += psum[r][t];
        g_vsum[bh * 64 + t] = s;
    }
    if (t < 32) {
        float lm = g_lmax[bh * 32 + t];
        float mx = lm;
        #pragma unroll
        for (int o = 16; o; o >>= 1) mx = fmaxf(mx, __shfl_xor_sync(0xffffffffu, mx, o));
        g_scale[bh * 32 + t] = ex2f(lm - mx);
    }
}

// ---------------------------------------------------------------------------
__global__ void k2_reduce() {
    const size_t NCTX = (size_t)BH * MFEAT * DHEAD;  // 1048576
    size_t idx = (size_t)blockIdx.x * 256 + threadIdx.x;
    if (idx < NCTX) {
        size_t bh = idx >> 14;
        size_t rem = idx & 16383;
        size_t feat = rem >> 6;
        size_t fh = feat >> 7;
        size_t e = idx & 63;
        float s = 0.f;
        #pragma unroll
        for (int c = 0; c < CH; c++)
            s += g_scale[bh * CH * 2 + c * 2 + fh] *
                 g_ctx_part[(((size_t)bh * CH + c) << 14) + rem];
        g_ctx[idx] = RATIO * (s + KEPS * g_vsum[(bh << 6) + e]);
    } else if (idx < NCTX + (size_t)BH * MFEAT) {
        size_t i2 = idx - NCTX;
        size_t bh = i2 >> 8, j = i2 & 255;
        size_t fh = j >> 7;
        float s = 0.f;
        #pragma unroll
        for (int c = 0; c < CH; c++)
            s += g_scale[bh * CH * 2 + c * 2 + fh] *
                 g_ksum_part[(bh * CH + c) * MFEAT + j];
        g_ksum[i2] = RATIO * (s + KEPS * (float)NSEQ);
    }
}

// ---------------------------------------------------------------------------
// k3: 128-row tiles, 8 rows/thread dd tiling, full-resident ctx (no chunking),
// vectorized exp phase, out-GEMM 4 rows x 8 e-cols per thread.
// smem: dds[128][264] @0 (135168) | overlay @135168:
//   phase1: qsm[128][64] (32768) @135168; Pth[64][132] (33792) @167936
//   phase2: ctx[256][64] (65536) @135168
// total 201728.
// ---------------------------------------------------------------------------
#define K3_SMEM_BYTES 201728

__global__ __launch_bounds__(256, 1) void k3_out(const float* __restrict__ Q,
                                                 const float* __restrict__ P,
                                                 float* __restrict__ O) {
    extern __shared__ __align__(16) char smraw[];
    float (*dds)[264] = (float (*)[264])smraw;             // [128][264]
    float (*qsm)[64]  = (float (*)[64])(smraw + 135168);   // [128][64], phase 1
    float* Pth        = (float*)(smraw + 167936);          // [64][132], phase 1
    float* ctxs       = (float*)(smraw + 135168);          // [256][64], phase 2
    __shared__ float ksum_s[256];
    __shared__ float diag[128];
    __shared__ float rmax[128];
    __shared__ float dinv[128];

    const int bh = blockIdx.y, tile = blockIdx.x, t = threadIdx.x;
    const int w = t >> 5, lane = t & 31;
    const int rg = (t >> 4) * 8;     // dd phase: 8 owned rows
    const int fg = (t & 15) * 4;     // dd phase: feature base per 64-block

    ksum_s[t] = g_ksum[bh * MFEAT + t];

    // Load Q tile (128 x 64) + per-row diag (log2 domain).
    {
        const float4* qb = (const float4*)(Q + ((size_t)bh * NSEQ + (size_t)tile * 128) * DHEAD);
        float4* qs = (float4*)&qsm[0][0];
        #pragma unroll
        for (int kq = 0; kq < 8; kq++) {
            int i = t + 256 * kq;          // float4 index; row = i >> 4
            float4 a = qb[i];
            qs[i] = a;
            float ss = a.x*a.x + a.y*a.y + a.z*a.z + a.w*a.w;
            #pragma unroll
            for (int o = 1; o < 16; o <<= 1) ss += __shfl_xor_sync(0xffffffffu, ss, o);
            if ((t & 15) == 0) diag[i >> 4] = HDN2_L2E * ss;
        }
    }

    // dd GEMM in two 128-feature halves; q cached in regs as float4-over-d.
    #pragma unroll 1
    for (int h = 0; h < 2; h++) {
        __syncthreads();
        for (int idx = t; idx < 128 * 64; idx += 256) {
            int f = idx >> 6, d = idx & 63;
            Pth[d * 132 + f] = DN_L2E * P[(size_t)(h * 128 + f) * 64 + d];
        }
        __syncthreads();

        u64 a0L[8], a0H[8], a1L[8], a1H[8];
        #pragma unroll
        for (int i = 0; i < 8; i++) { a0L[i]=0; a0H[i]=0; a1L[i]=0; a1H[i]=0; }

        #pragma unroll 2
        for (int db = 0; db < 64; db += 4) {
            float4 qv[8];
            #pragma unroll
            for (int i = 0; i < 8; i++) qv[i] = *(const float4*)&qsm[rg + i][db];
            #pragma unroll
            for (int dq = 0; dq < 4; dq++) {
                const float* prow = Pth + (db + dq) * 132 + fg;
                ulonglong2 pv0 = *(const ulonglong2*)prow;
                ulonglong2 pv1 = *(const ulonglong2*)(prow + 64);
                #pragma unroll
                for (int i = 0; i < 8; i++) {
                    float qsv = (dq == 0) ? qv[i].x : (dq == 1) ? qv[i].y
                              : (dq == 2) ? qv[i].z : qv[i].w;
                    u64 qp = pack2(qsv, qsv);
                    a0L[i] = ffma2(qp, pv0.x, a0L[i]);
                    a0H[i] = ffma2(qp, pv0.y, a0H[i]);
                    a1L[i] = ffma2(qp, pv1.x, a1L[i]);
                    a1H[i] = ffma2(qp, pv1.y, a1H[i]);
                }
            }
        }
        #pragma unroll
        for (int i = 0; i < 8; i++) {
            float2 l0 = unpack2(a0L[i]), h0 = unpack2(a0H[i]);
            float2 l1 = unpack2(a1L[i]), h1 = unpack2(a1H[i]);
            *(float4*)&dds[rg + i][h * 128 + fg]      = make_float4(l0.x, l0.y, h0.x, h0.y);
            *(float4*)&dds[rg + i][h * 128 + 64 + fg] = make_float4(l1.x, l1.y, h1.x, h1.y);
        }
    }
    __syncthreads();   // qsm/Pth dead after this point

    // Full ctx load (64KB), hidden under rmax/exp/dinv phases.
    const uint32_t ctx_s = (uint32_t)__cvta_generic_to_shared(ctxs);
    const float* cgb = g_ctx + (size_t)bh * MFEAT * DHEAD;
    {
        #pragma unroll
        for (int q = 0; q < 16; q++) {
            int i = t + 256 * q;          // float4 index over 16384 floats
            cp_async16(ctx_s + i * 16, cgb + i * 4);
        }
        cp_commit();
    }

    // Per-row max (16 rows per warp).
    #pragma unroll
    for (int rr = 0; rr < 16; rr++) {
        int r = w * 16 + rr;
        float m = dds[r][lane];
        #pragma unroll
        for (int c = 1; c < 8; c++) m = fmaxf(m, dds[r][lane + 32 * c]);
        #pragma unroll
        for (int o = 16; o; o >>= 1) m = fmaxf(m, __shfl_xor_sync(0xffffffffu, m, o));
        if (lane == 0) rmax[r] = m;
    }
    __syncthreads();

    // q' in place, vectorized: thread = 4 cols x 32 rows. Split poly/MUFU by row pair.
    {
        const int cg = (t & 63) * 4;
        const int rb = (t >> 6) * 32;
        #pragma unroll 4
        for (int rr = 0; rr < 32; rr++) {
            int r = rb + rr;
            float4 yv = *(const float4*)&dds[r][cg];
            float off = diag[r] + rmax[r];
            float y0 = yv.x - off, y1 = yv.y - off;
            float y2 = yv.z - off, y3 = yv.w - off;
            float k0, k1, k2, k3;
            if (((r >> 1) & 1) == 0) {
                float2 a = unpack2(exp2_poly2(y0, y1));
                float2 b = unpack2(exp2_poly2(y2, y3));
                k0 = a.x; k1 = a.y; k2 = b.x; k3 = b.y;
            } else {
                k0 = ex2f(y0); k1 = ex2f(y1); k2 = ex2f(y2); k3 = ex2f(y3);
            }
            *(float4*)&dds[r][cg] = make_float4(
                RATIO * (k0 + KEPS), RATIO * (k1 + KEPS),
                RATIO * (k2 + KEPS), RATIO * (k3 + KEPS));
        }
    }
    __syncthreads();

    // D_inv (16 rows per warp).
    #pragma unroll
    for (int rr = 0; rr < 16; rr++) {
        int r = w * 16 + rr;
        float s = 0.f;
        #pragma unroll
        for (int c = 0; c < 8; c++)
            s = fmaf(dds[r][lane + 32 * c], ksum_s[lane + 32 * c], s);
        #pragma unroll
        for (int o = 16; o; o >>= 1) s += __shfl_xor_sync(0xffffffffu, s, o);
        if (lane == 0) dinv[r] = 1.0f / s;
    }
    cp_wait0();
    __syncthreads();   // ctx + dinv visible

    // out GEMM: 4 rows x 8 e-cols per thread; single uninterrupted j-loop.
    const int rg2 = (t >> 3) * 4;    // rows rg2..rg2+3
    const int eg  = (t & 7) * 8;     // e-cols eg..eg+7
    u64 oacc[4][4];
    #pragma unroll
    for (int i = 0; i < 4; i++)
        #pragma unroll
        for (int j = 0; j < 4; j++) oacc[i][j] = 0ull;

    #pragma unroll 2
    for (int jb = 0; jb < 256; jb += 4) {
        float4 qv[4];
        #pragma unroll
        for (int i = 0; i < 4; i++) qv[i] = *(const float4*)&dds[rg2 + i][jb];
        #pragma unroll
        for (int jj = 0; jj < 4; jj++) {
            const float* crow = ctxs + (jb + jj) * 64 + eg;
            ulonglong2 cv0 = *(const ulonglong2*)crow;
            ulonglong2 cv1 = *(const ulonglong2*)(crow + 4);
            #pragma unroll
            for (int i = 0; i < 4; i++) {
                float s = (jj == 0) ? qv[i].x : (jj == 1) ? qv[i].y
                        : (jj == 2) ? qv[i].z : qv[i].w;
                u64 p = pack2(s, s);
                oacc[i][0] = ffma2(p, cv0.x, oacc[i][0]);
                oacc[i][1] = ffma2(p, cv0.y, oacc[i][1]);
                oacc[i][2] = ffma2(p, cv1.x, oacc[i][2]);
                oacc[i][3] = ffma2(p, cv1.y, oacc[i][3]);
            }
        }
    }

    const size_t rowbase = (size_t)bh * NSEQ + (size_t)tile * 128;
    #pragma unroll
    for (int i = 0; i < 4; i++) {
        float dv = dinv[rg2 + i];
        u64 d2 = pack2(dv, dv);
        float* ob = O + (rowbase + rg2 + i) * DHEAD + eg;
        ((ulonglong2*)ob)[0] = make_ulonglong2(fmul2(oacc[i][0], d2), fmul2(oacc[i][1], d2));
        ((ulonglong2*)ob)[1] = make_ulonglong2(fmul2(oacc[i][2], d2), fmul2(oacc[i][3], d2));
    }
}

// ---------------------------------------------------------------------------
extern "C" void kernel_launch(void* const* d_in, const int* in_sizes, int n_in,
                              void* d_out, int out_size) {
    const float* q    = (const float*)d_in[0];
    const float* k    = (const float*)d_in[1];
    const float* v    = (const float*)d_in[2];
    const float* proj = (const float*)d_in[3];
    float* out = (float*)d_out;

    cudaFuncSetAttribute(k12_ctx, cudaFuncAttributeMaxDynamicSharedMemorySize, K12_SMEM);
    cudaFuncSetAttribute(k3_out, cudaFuncAttributeMaxDynamicSharedMemorySize, K3_SMEM_BYTES);

    // Launch order keeps k3 at ncu slot 5.
    k12_ctx<<<dim3(CH * 2, BH), 256, K12_SMEM>>>(k, v, proj);
    kvsum<<<BH, 256>>>(v);
    {
        const size_t total = (size_t)BH * MFEAT * DHEAD + (size_t)BH * MFEAT;
        k2_reduce<<<(unsigned)((total + 255) / 256), 256>>>();
    }
    k3_out<<<dim3(NSEQ / 128, BH), 256, K3_SMEM_BYTES>>>(q, proj, out);
}

// round 16
// speedup vs baseline: 1.1111x; 1.1111x over previous
#include <cuda_runtime.h>
#include <cstdint>
#include <math.h>

// Problem constants
#define BH 64
#define NSEQ 4096
#define DHEAD 64
#define MFEAT 256
#define RATIO 0.0625f             // 256^-0.5
#define KEPS 1e-4f
#define CH 16                     // row-chunks for k12 (256 rows each)
#define STAGES 8                  // 256/32 rows per stage

// log2-domain constants
#define DN_L2E   0.510069723f     // 64^-0.25 * log2(e)
#define HDN2_L2E 0.0901684401f    // 0.5 * 64^-0.5 * log2(e)

typedef unsigned long long u64;

// MUFU exp2 (guaranteed EX2.APPROX)
__device__ __forceinline__ float ex2f(float x) {
    float y; asm("ex2.approx.f32 %0, %1;" : "=f"(y) : "f"(x)); return y;
}

// Packed fp32x2 helpers
__device__ __forceinline__ u64 ffma2(u64 a, u64 b, u64 c) {
    u64 d;
    asm("fma.rn.f32x2 %0, %1, %2, %3;" : "=l"(d) : "l"(a), "l"(b), "l"(c));
    return d;
}
__device__ __forceinline__ u64 fmul2(u64 a, u64 b) {
    u64 d;
    asm("mul.rn.f32x2 %0, %1, %2;" : "=l"(d) : "l"(a), "l"(b));
    return d;
}
__device__ __forceinline__ u64 fadd2(u64 a, u64 b) {
    u64 d;
    asm("add.rn.f32x2 %0, %1, %2;" : "=l"(d) : "l"(a), "l"(b));
    return d;
}
__device__ __forceinline__ u64 pack2(float lo, float hi) {
    u64 d; asm("mov.b64 %0, {%1, %2};" : "=l"(d) : "f"(lo), "f"(hi)); return d;
}
__device__ __forceinline__ float2 unpack2(u64 v) {
    float lo, hi; asm("mov.b64 {%0, %1}, %2;" : "=f"(lo), "=f"(hi) : "l"(v));
    return make_float2(lo, hi);
}

// Packed exp2 on the FMA pipe (degree-5 poly, rel err ~2e-6).
__device__ __forceinline__ u64 exp2_poly2(float y0, float y1) {
    y0 = fmaxf(y0, -120.f);
    y1 = fmaxf(y1, -120.f);
    u64 y = pack2(y0, y1);
    const u64 C  = pack2(12582912.f, 12582912.f);    // 1.5*2^23
    const u64 nC = pack2(-12582912.f, -12582912.f);
    const u64 n1 = pack2(-1.f, -1.f);
    u64 z  = fadd2(y, C);
    u64 iz = fadd2(z, nC);
    u64 f  = ffma2(iz, n1, y);
    u64 p  = pack2(0.00133335581f, 0.00133335581f);
    p = ffma2(p, f, pack2(0.00961812911f, 0.00961812911f));
    p = ffma2(p, f, pack2(0.05550410866f, 0.05550410866f));
    p = ffma2(p, f, pack2(0.24022650696f, 0.24022650696f));
    p = ffma2(p, f, pack2(0.69314718056f, 0.69314718056f));
    p = ffma2(p, f, pack2(1.f, 1.f));
    uint32_t zlo, zhi;
    asm("mov.b64 {%0,%1}, %2;" : "=r"(zlo), "=r"(zhi) : "l"(z));
    uint32_t slo = zlo * 8388608u + 0x3F800000u;
    uint32_t shi = zhi * 8388608u + 0x3F800000u;
    u64 s; asm("mov.b64 %0, {%1,%2};" : "=l"(s) : "r"(slo), "r"(shi));
    return fmul2(p, s);
}

// cp.async helpers
__device__ __forceinline__ void cp_async16(uint32_t s, const void* g) {
    asm volatile("cp.async.cg.shared.global [%0], [%1], 16;" :: "r"(s), "l"(g));
}
__device__ __forceinline__ void cp_commit() {
    asm volatile("cp.async.commit_group;" ::: "memory");
}
__device__ __forceinline__ void cp_wait0() {
    asm volatile("cp.async.wait_group 0;" ::: "memory");
}

// Scratch (device globals). All entries fully rewritten each call.
__device__ float g_ctx_part[(size_t)BH * CH * MFEAT * DHEAD]; // 67 MB
__device__ float g_ksum_part[BH * CH * MFEAT];
__device__ float g_lmax[BH * CH * 2];     // log2-domain
__device__ float g_scale[BH * CH * 2];
__device__ float g_vsum[BH * DHEAD];
__device__ float g_ctx[(size_t)BH * MFEAT * DHEAD];           // 4 MB
__device__ float g_ksum[BH * MFEAT];

// ---------------------------------------------------------------------------
// k12: fused K-features + partial ctx/ksum (unchanged, passing).
// ---------------------------------------------------------------------------
#define K12_SMEM 84480

__global__ __launch_bounds__(256, 2) void k12_ctx(const float* __restrict__ K,
                                                  const float* __restrict__ V,
                                                  const float* __restrict__ P) {
    extern __shared__ __align__(16) char smraw[];
    float* Pt  = (float*)smraw;                    // [64][132]
    float* Ks  = (float*)(smraw + 33792);          // [2][32][68]
    float* Vs  = (float*)(smraw + 51200);          // [2][32][64]
    float* kps = (float*)(smraw + 67584);          // [32][132]
    __shared__ float wmax[8];

    const int bh = blockIdx.y;
    const int chunk = blockIdx.x >> 1;
    const int fh = blockIdx.x & 1;
    const int fbase = fh * 128;
    const int t = threadIdx.x;
    const int w = t >> 5, lane = t & 31;
    const int fgrp = (w & 3) * 32 + (lane & 7) * 4;
    const int egrp = (w >> 2) * 32 + (lane >> 3) * 8;

    const float* kb = K + ((size_t)bh * NSEQ + (size_t)chunk * 256) * 64;
    const float* vb = V + ((size_t)bh * NSEQ + (size_t)chunk * 256) * 64;

    uint32_t ks_s = (uint32_t)__cvta_generic_to_shared(Ks);
    uint32_t vs_s = (uint32_t)__cvta_generic_to_shared(Vs);

    {
        int c0 = t, c1 = t + 256;
        int r0 = c0 >> 4, q0 = c0 & 15, r1 = c1 >> 4, q1 = c1 & 15;
        cp_async16(ks_s + r0 * 272 + q0 * 16, kb + r0 * 64 + q0 * 4);
        cp_async16(ks_s + r1 * 272 + q1 * 16, kb + r1 * 64 + q1 * 4);
        cp_async16(vs_s + r0 * 256 + q0 * 16, vb + r0 * 64 + q0 * 4);
        cp_async16(vs_s + r1 * 256 + q1 * 16, vb + r1 * 64 + q1 * 4);
        cp_commit();
    }

    for (int idx = t; idx < 128 * 64; idx += 256) {
        int f = idx >> 6, d = idx & 63;
        Pt[d * 132 + f] = DN_L2E * P[(size_t)(fbase + f) * 64 + d];
    }

    u64 ctx2[16];
    #pragma unroll
    for (int i = 0; i < 16; i++) ctx2[i] = 0ull;
    float ks0 = 0.f, ks1 = 0.f, ks2 = 0.f, ks3 = 0.f;
    float M = -1e30f;

    for (int st = 0; st < STAGES; st++) {
        const int buf = st & 1;
        cp_wait0();
        __syncthreads();

        if (st + 1 < STAGES) {
            const float* kn = kb + (st + 1) * 32 * 64;
            const float* vn = vb + (st + 1) * 32 * 64;
            uint32_t kd = ks_s + (buf ^ 1) * 8704;
            uint32_t vd = vs_s + (buf ^ 1) * 8192;
            int c0 = t, c1 = t + 256;
            int r0 = c0 >> 4, q0 = c0 & 15, r1 = c1 >> 4, q1 = c1 & 15;
            cp_async16(kd + r0 * 272 + q0 * 16, kn + r0 * 64 + q0 * 4);
            cp_async16(kd + r1 * 272 + q1 * 16, kn + r1 * 64 + q1 * 4);
            cp_async16(vd + r0 * 256 + q0 * 16, vn + r0 * 64 + q0 * 4);
            cp_async16(vd + r1 * 256 + q1 * 16, vn + r1 * 64 + q1 * 4);
            cp_commit();
        }

        const float* ksb = Ks + buf * 2176;
        const float* vsb = Vs + buf * 2048;

        float diag_r[4];
        #pragma unroll
        for (int i = 0; i < 4; i++) {
            const float* kr = ksb + (w * 4 + i) * 68;
            float2 v2 = *(const float2*)(kr + 2 * lane);
            float ss = v2.x * v2.x + v2.y * v2.y;
            #pragma unroll
            for (int o = 16; o; o >>= 1) ss += __shfl_xor_sync(0xffffffffu, ss, o);
            diag_r[i] = HDN2_L2E * ss;
        }

        u64 acc[4][2];
        #pragma unroll
        for (int i = 0; i < 4; i++) { acc[i][0] = 0ull; acc[i][1] = 0ull; }
        const float* kr0 = ksb + (w * 4 + 0) * 68;
        const float* kr1 = ksb + (w * 4 + 1) * 68;
        const float* kr2 = ksb + (w * 4 + 2) * 68;
        const float* kr3 = ksb + (w * 4 + 3) * 68;
        #pragma unroll 4
        for (int d = 0; d < 64; d += 4) {
            float4 k0 = *(const float4*)(kr0 + d);
            float4 k1 = *(const float4*)(kr1 + d);
            float4 k2 = *(const float4*)(kr2 + d);
            float4 k3 = *(const float4*)(kr3 + d);
            #pragma unroll
            for (int q = 0; q < 4; q++) {
                ulonglong2 pv = *(const ulonglong2*)(Pt + (d + q) * 132 + lane * 4);
                float kq0 = (q == 0) ? k0.x : (q == 1) ? k0.y : (q == 2) ? k0.z : k0.w;
                float kq1 = (q == 0) ? k1.x : (q == 1) ? k1.y : (q == 2) ? k1.z : k1.w;
                float kq2 = (q == 0) ? k2.x : (q == 1) ? k2.y : (q == 2) ? k2.z : k2.w;
                float kq3 = (q == 0) ? k3.x : (q == 1) ? k3.y : (q == 2) ? k3.z : k3.w;
                u64 b0 = pack2(kq0, kq0), b1 = pack2(kq1, kq1);
                u64 b2 = pack2(kq2, kq2), b3 = pack2(kq3, kq3);
                acc[0][0] = ffma2(b0, pv.x, acc[0][0]); acc[0][1] = ffma2(b0, pv.y, acc[0][1]);
                acc[1][0] = ffma2(b1, pv.x, acc[1][0]); acc[1][1] = ffma2(b1, pv.y, acc[1][1]);
                acc[2][0] = ffma2(b2, pv.x, acc[2][0]); acc[2][1] = ffma2(b2, pv.y, acc[2][1]);
                acc[3][0] = ffma2(b3, pv.x, acc[3][0]); acc[3][1] = ffma2(b3, pv.y, acc[3][1]);
            }
        }

        float dd[4][4];
        float mx = -1e30f;
        #pragma unroll
        for (int i = 0; i < 4; i++) {
            float2 lo = unpack2(acc[i][0]);
            float2 hi = unpack2(acc[i][1]);
            dd[i][0] = lo.x; dd[i][1] = lo.y;
            dd[i][2] = hi.x; dd[i][3] = hi.y;
            mx = fmaxf(mx, fmaxf(fmaxf(dd[i][0], dd[i][1]), fmaxf(dd[i][2], dd[i][3])));
        }
        #pragma unroll
        for (int o = 16; o; o >>= 1) mx = fmaxf(mx, __shfl_xor_sync(0xffffffffu, mx, o));
        if (lane == 0) wmax[w] = mx;
        __syncthreads();
        float smax = wmax[0];
        #pragma unroll
        for (int i = 1; i < 8; i++) smax = fmaxf(smax, wmax[i]);

        if (smax > M) {
            float sc = ex2f(M - smax);
            u64 sc2 = pack2(sc, sc);
            #pragma unroll
            for (int i = 0; i < 16; i++) ctx2[i] = fmul2(ctx2[i], sc2);
            ks0 *= sc; ks1 *= sc; ks2 *= sc; ks3 *= sc;
            M = smax;
        }

        #pragma unroll
        for (int i = 0; i < 4; i++) {
            float dmi = diag_r[i] + M;
            float k0, k1, k2v, k3v;
            if ((i & 1) == 0) {
                u64 ea = exp2_poly2(dd[i][0] - dmi, dd[i][1] - dmi);
                u64 eb = exp2_poly2(dd[i][2] - dmi, dd[i][3] - dmi);
                float2 fa = unpack2(ea), fb = unpack2(eb);
                k0 = fa.x; k1 = fa.y; k2v = fb.x; k3v = fb.y;
            } else {
                k0  = ex2f(dd[i][0] - dmi);
                k1  = ex2f(dd[i][1] - dmi);
                k2v = ex2f(dd[i][2] - dmi);
                k3v = ex2f(dd[i][3] - dmi);
            }
            ks0 += k0; ks1 += k1; ks2 += k2v; ks3 += k3v;
            *(float4*)(kps + (w * 4 + i) * 132 + lane * 4) = make_float4(k0, k1, k2v, k3v);
        }
        __syncthreads();

        #pragma unroll 4
        for (int r = 0; r < 32; r++) {
            ulonglong2 kp4 = *(const ulonglong2*)(kps + r * 132 + fgrp);
            float2 klo = unpack2(kp4.x), khi = unpack2(kp4.y);
            u64 b0 = pack2(klo.x, klo.x), b1 = pack2(klo.y, klo.y);
            u64 b2 = pack2(khi.x, khi.x), b3 = pack2(khi.y, khi.y);
            const ulonglong2* vp = (const ulonglong2*)(vsb + r * 64 + egrp);
            ulonglong2 vA = vp[0], vB = vp[1];
            ctx2[0]  = ffma2(b0, vA.x, ctx2[0]);  ctx2[1]  = ffma2(b0, vA.y, ctx2[1]);
            ctx2[2]  = ffma2(b0, vB.x, ctx2[2]);  ctx2[3]  = ffma2(b0, vB.y, ctx2[3]);
            ctx2[4]  = ffma2(b1, vA.x, ctx2[4]);  ctx2[5]  = ffma2(b1, vA.y, ctx2[5]);
            ctx2[6]  = ffma2(b1, vB.x, ctx2[6]);  ctx2[7]  = ffma2(b1, vB.y, ctx2[7]);
            ctx2[8]  = ffma2(b2, vA.x, ctx2[8]);  ctx2[9]  = ffma2(b2, vA.y, ctx2[9]);
            ctx2[10] = ffma2(b2, vB.x, ctx2[10]); ctx2[11] = ffma2(b2, vB.y, ctx2[11]);
            ctx2[12] = ffma2(b3, vA.x, ctx2[12]); ctx2[13] = ffma2(b3, vA.y, ctx2[13]);
            ctx2[14] = ffma2(b3, vB.x, ctx2[14]); ctx2[15] = ffma2(b3, vB.y, ctx2[15]);
        }
    }

    __syncthreads();

    {
        float* base = g_ctx_part + ((size_t)(bh * CH + chunk) * MFEAT) * DHEAD;
        #pragma unroll
        for (int j = 0; j < 4; j++) {
            float* op = base + (size_t)(fbase + fgrp + j) * DHEAD + egrp;
            ((ulonglong2*)op)[0] = make_ulonglong2(ctx2[j * 4 + 0], ctx2[j * 4 + 1]);
            ((ulonglong2*)op)[1] = make_ulonglong2(ctx2[j * 4 + 2], ctx2[j * 4 + 3]);
        }
    }

    *(float4*)(kps + w * 128 + lane * 4) = make_float4(ks0, ks1, ks2, ks3);
    __syncthreads();
    if (t < 128) {
        float s = 0.f;
        #pragma unroll
        for (int w2 = 0; w2 < 8; w2++) s += kps[w2 * 128 + t];
        g_ksum_part[(bh * CH + chunk) * MFEAT + fbase + t] = s;
    }
    if (t == 0) g_lmax[(bh * CH + chunk) * 2 + fh] = M;
}

// ---------------------------------------------------------------------------
// kvsum: vsum + folded kscale (unchanged).
// ---------------------------------------------------------------------------
__global__ __launch_bounds__(256) void kvsum(const float* __restrict__ V) {
    __shared__ float psum[16][64];
    const int bh = blockIdx.x, t = threadIdx.x;
    const int e4 = t & 15, rc = t >> 4;
    const float4* vb = (const float4*)V + (size_t)bh * NSEQ * 16;
    float4 acc = make_float4(0.f, 0.f, 0.f, 0.f);
    #pragma unroll 8
    for (int it = 0; it < 256; it++) {
        float4 a = vb[(size_t)(rc + 16 * it) * 16 + e4];
        acc.x += a.x; acc.y += a.y; acc.z += a.z; acc.w += a.w;
    }
    psum[rc][e4*4+0] = acc.x; psum[rc][e4*4+1] = acc.y;
    psum[rc][e4*4+2] = acc.z; psum[rc][e4*4+3] = acc.w;
    __syncthreads();
    if (t < 64) {
        float s = 0.f;
        #pragma unroll
        for (int r = 0; r < 16; r++) s += psum[r][t];
        g_vsum[bh * 64 + t] = s;
    }
    if (t < 32) {
        float lm = g_lmax[bh * 32 + t];
        float mx = lm;
        #pragma unroll
        for (int o = 16; o; o >>= 1) mx = fmaxf(mx, __shfl_xor_sync(0xffffffffu, mx, o));
        g_scale[bh * 32 + t] = ex2f(lm - mx);
    }
}

// ---------------------------------------------------------------------------
__global__ void k2_reduce() {
    const size_t NCTX = (size_t)BH * MFEAT * DHEAD;  // 1048576
    size_t idx = (size_t)blockIdx.x * 256 + threadIdx.x;
    if (idx < NCTX) {
        size_t bh = idx >> 14;
        size_t rem = idx & 16383;
        size_t feat = rem >> 6;
        size_t fh = feat >> 7;
        size_t e = idx & 63;
        float s = 0.f;
        #pragma unroll
        for (int c = 0; c < CH; c++)
            s += g_scale[bh * CH * 2 + c * 2 + fh] *
                 g_ctx_part[(((size_t)bh * CH + c) << 14) + rem];
        g_ctx[idx] = RATIO * (s + KEPS * g_vsum[(bh << 6) + e]);
    } else if (idx < NCTX + (size_t)BH * MFEAT) {
        size_t i2 = idx - NCTX;
        size_t bh = i2 >> 8, j = i2 & 255;
        size_t fh = j >> 7;
        float s = 0.f;
        #pragma unroll
        for (int c = 0; c < CH; c++)
            s += g_scale[bh * CH * 2 + c * 2 + fh] *
                 g_ksum_part[(bh * CH + c) * MFEAT + j];
        g_ksum[i2] = RATIO * (s + KEPS * (float)NSEQ);
    }
}

// ---------------------------------------------------------------------------
// k3: 128-row tiles; r14 dd/exp/dinv phases; full-resident ctx; bank-audited
// out-GEMM: thread owns rows {g,g+32,g+64,g+96} x cols {e4..e4+3, e4+32..+35}.
// smem: dds[128][264] @0 (135168) | overlay @135168:
//   phase1: qsm[128][64] (32768) @135168; Pth[64][132] (33792) @167936
//   phase2: ctx[256][64] (65536) @135168
// total 201728.
// ---------------------------------------------------------------------------
#define K3_SMEM_BYTES 201728

__global__ __launch_bounds__(256, 1) void k3_out(const float* __restrict__ Q,
                                                 const float* __restrict__ P,
                                                 float* __restrict__ O) {
    extern __shared__ __align__(16) char smraw[];
    float (*dds)[264] = (float (*)[264])smraw;             // [128][264]
    float (*qsm)[64]  = (float (*)[64])(smraw + 135168);   // [128][64], phase 1
    float* Pth        = (float*)(smraw + 167936);          // [64][132], phase 1
    float* ctxs       = (float*)(smraw + 135168);          // [256][64], phase 2
    __shared__ float ksum_s[256];
    __shared__ float diag[128];
    __shared__ float rmax[128];
    __shared__ float dinv[128];

    const int bh = blockIdx.y, tile = blockIdx.x, t = threadIdx.x;
    const int w = t >> 5, lane = t & 31;
    const int rg = (t >> 4) * 8;     // dd phase: 8 owned rows
    const int fg = (t & 15) * 4;     // dd phase: feature base per 64-block

    ksum_s[t] = g_ksum[bh * MFEAT + t];

    // Load Q tile (128 x 64) + per-row diag (log2 domain).
    {
        const float4* qb = (const float4*)(Q + ((size_t)bh * NSEQ + (size_t)tile * 128) * DHEAD);
        float4* qs = (float4*)&qsm[0][0];
        #pragma unroll
        for (int kq = 0; kq < 8; kq++) {
            int i = t + 256 * kq;          // float4 index; row = i >> 4
            float4 a = qb[i];
            qs[i] = a;
            float ss = a.x*a.x + a.y*a.y + a.z*a.z + a.w*a.w;
            #pragma unroll
            for (int o = 1; o < 16; o <<= 1) ss += __shfl_xor_sync(0xffffffffu, ss, o);
            if ((t & 15) == 0) diag[i >> 4] = HDN2_L2E * ss;
        }
    }

    // dd GEMM in two 128-feature halves; q cached in regs as float4-over-d.
    #pragma unroll 1
    for (int h = 0; h < 2; h++) {
        __syncthreads();
        for (int idx = t; idx < 128 * 64; idx += 256) {
            int f = idx >> 6, d = idx & 63;
            Pth[d * 132 + f] = DN_L2E * P[(size_t)(h * 128 + f) * 64 + d];
        }
        __syncthreads();

        u64 a0L[8], a0H[8], a1L[8], a1H[8];
        #pragma unroll
        for (int i = 0; i < 8; i++) { a0L[i]=0; a0H[i]=0; a1L[i]=0; a1H[i]=0; }

        #pragma unroll 2
        for (int db = 0; db < 64; db += 4) {
            float4 qv[8];
            #pragma unroll
            for (int i = 0; i < 8; i++) qv[i] = *(const float4*)&qsm[rg + i][db];
            #pragma unroll
            for (int dq = 0; dq < 4; dq++) {
                const float* prow = Pth + (db + dq) * 132 + fg;
                ulonglong2 pv0 = *(const ulonglong2*)prow;
                ulonglong2 pv1 = *(const ulonglong2*)(prow + 64);
                #pragma unroll
                for (int i = 0; i < 8; i++) {
                    float qsv = (dq == 0) ? qv[i].x : (dq == 1) ? qv[i].y
                              : (dq == 2) ? qv[i].z : qv[i].w;
                    u64 qp = pack2(qsv, qsv);
                    a0L[i] = ffma2(qp, pv0.x, a0L[i]);
                    a0H[i] = ffma2(qp, pv0.y, a0H[i]);
                    a1L[i] = ffma2(qp, pv1.x, a1L[i]);
                    a1H[i] = ffma2(qp, pv1.y, a1H[i]);
                }
            }
        }
        #pragma unroll
        for (int i = 0; i < 8; i++) {
            float2 l0 = unpack2(a0L[i]), h0 = unpack2(a0H[i]);
            float2 l1 = unpack2(a1L[i]), h1 = unpack2(a1H[i]);
            *(float4*)&dds[rg + i][h * 128 + fg]      = make_float4(l0.x, l0.y, h0.x, h0.y);
            *(float4*)&dds[rg + i][h * 128 + 64 + fg] = make_float4(l1.x, l1.y, h1.x, h1.y);
        }
    }
    __syncthreads();   // qsm/Pth dead after this point

    // Full ctx load (64KB), hidden under rmax/exp/dinv phases.
    const uint32_t ctx_s = (uint32_t)__cvta_generic_to_shared(ctxs);
    const float* cgb = g_ctx + (size_t)bh * MFEAT * DHEAD;
    {
        #pragma unroll
        for (int q = 0; q < 16; q++) {
            int i = t + 256 * q;          // float4 index over 16384 floats
            cp_async16(ctx_s + i * 16, cgb + i * 4);
        }
        cp_commit();
    }

    // Per-row max (16 rows per warp).
    #pragma unroll
    for (int rr = 0; rr < 16; rr++) {
        int r = w * 16 + rr;
        float m = dds[r][lane];
        #pragma unroll
        for (int c = 1; c < 8; c++) m = fmaxf(m, dds[r][lane + 32 * c]);
        #pragma unroll
        for (int o = 16; o; o >>= 1) m = fmaxf(m, __shfl_xor_sync(0xffffffffu, m, o));
        if (lane == 0) rmax[r] = m;
    }
    __syncthreads();

    // q' in place: exp2 split 1/2 poly, 1/2 MUFU (r14 scalar form).
    #pragma unroll 4
    for (int pr = 0; pr < 64; pr++) {
        int r = pr * 2;
        float y0 = dds[r][t]     - (diag[r]     + rmax[r]);
        float y1 = dds[r + 1][t] - (diag[r + 1] + rmax[r + 1]);
        float k0, k1;
        if ((pr & 1) == 0) {
            float2 ee = unpack2(exp2_poly2(y0, y1));
            k0 = ee.x; k1 = ee.y;
        } else {
            k0 = ex2f(y0); k1 = ex2f(y1);
        }
        dds[r][t]     = RATIO * (k0 + KEPS);
        dds[r + 1][t] = RATIO * (k1 + KEPS);
    }
    __syncthreads();

    // D_inv (16 rows per warp).
    #pragma unroll
    for (int rr = 0; rr < 16; rr++) {
        int r = w * 16 + rr;
        float s = 0.f;
        #pragma unroll
        for (int c = 0; c < 8; c++)
            s = fmaf(dds[r][lane + 32 * c], ksum_s[lane + 32 * c], s);
        #pragma unroll
        for (int o = 16; o; o >>= 1) s += __shfl_xor_sync(0xffffffffu, s, o);
        if (lane == 0) dinv[r] = 1.0f / s;
    }
    cp_wait0();
    __syncthreads();   // ctx + dinv visible

    // out GEMM: rows {g, g+32, g+64, g+96}, cols {e4..e4+3, e4+32..e4+35}.
    // qv loads: 4 consecutive rows per warp at 264-float stride -> banks
    // {0,8,16,24} -> conflict-free. ctx loads: 8x16B contiguous -> 1 wf.
    const int g  = t >> 3;           // 0..31
    const int e4 = (t & 7) * 4;      // 0..28
    u64 oacc[4][4];                  // [row i][cv0.x, cv0.y, cv1.x, cv1.y]
    #pragma unroll
    for (int i = 0; i < 4; i++)
        #pragma unroll
        for (int j = 0; j < 4; j++) oacc[i][j] = 0ull;

    #pragma unroll 2
    for (int jb = 0; jb < 256; jb += 4) {
        float4 qv[4];
        #pragma unroll
        for (int i = 0; i < 4; i++) qv[i] = *(const float4*)&dds[g + 32 * i][jb];
        #pragma unroll
        for (int jj = 0; jj < 4; jj++) {
            const float* crow = ctxs + (jb + jj) * 64;
            ulonglong2 cv0 = *(const ulonglong2*)(crow + e4);
            ulonglong2 cv1 = *(const ulonglong2*)(crow + e4 + 32);
            #pragma unroll
            for (int i = 0; i < 4; i++) {
                float s = (jj == 0) ? qv[i].x : (jj == 1) ? qv[i].y
                        : (jj == 2) ? qv[i].z : qv[i].w;
                u64 p = pack2(s, s);
                oacc[i][0] = ffma2(p, cv0.x, oacc[i][0]);
                oacc[i][1] = ffma2(p, cv0.y, oacc[i][1]);
                oacc[i][2] = ffma2(p, cv1.x, oacc[i][2]);
                oacc[i][3] = ffma2(p, cv1.y, oacc[i][3]);
            }
        }
    }

    const size_t rowbase = (size_t)bh * NSEQ + (size_t)tile * 128;
    #pragma unroll
    for (int i = 0; i < 4; i++) {
        int r = g + 32 * i;
        float dv = dinv[r];
        u64 d2 = pack2(dv, dv);
        float* ob = O + (rowbase + r) * DHEAD;
        *(ulonglong2*)(ob + e4)      = make_ulonglong2(fmul2(oacc[i][0], d2), fmul2(oacc[i][1], d2));
        *(ulonglong2*)(ob + e4 + 32) = make_ulonglong2(fmul2(oacc[i][2], d2), fmul2(oacc[i][3], d2));
    }
}

// ---------------------------------------------------------------------------
extern "C" void kernel_launch(void* const* d_in, const int* in_sizes, int n_in,
                              void* d_out, int out_size) {
    const float* q    = (const float*)d_in[0];
    const float* k    = (const float*)d_in[1];
    const float* v    = (const float*)d_in[2];
    const float* proj = (const float*)d_in[3];
    float* out = (float*)d_out;

    cudaFuncSetAttribute(k12_ctx, cudaFuncAttributeMaxDynamicSharedMemorySize, K12_SMEM);
    cudaFuncSetAttribute(k3_out, cudaFuncAttributeMaxDynamicSharedMemorySize, K3_SMEM_BYTES);

    // Launch order keeps k3 at ncu slot 5.
    k12_ctx<<<dim3(CH * 2, BH), 256, K12_SMEM>>>(k, v, proj);
    kvsum<<<BH, 256>>>(v);
    {
        const size_t total = (size_t)BH * MFEAT * DHEAD + (size_t)BH * MFEAT;
        k2_reduce<<<(unsigned)((total + 255) / 256), 256>>>();
    }
    k3_out<<<dim3(NSEQ / 128, BH), 256, K3_SMEM_BYTES>>>(q, proj, out);
}

// round 17
// speedup vs baseline: 1.1522x; 1.0370x over previous
#include <cuda_runtime.h>
#include <cstdint>
#include <math.h>

// Problem constants
#define BH 64
#define NSEQ 4096
#define DHEAD 64
#define MFEAT 256
#define RATIO 0.0625f             // 256^-0.5
#define KEPS 1e-4f
#define CH 16                     // row-chunks for k12 (256 rows each)
#define STAGES 8                  // 256/32 rows per stage

// log2-domain constants
#define DN_L2E   0.510069723f     // 64^-0.25 * log2(e)
#define HDN2_L2E 0.0901684401f    // 0.5 * 64^-0.5 * log2(e)

typedef unsigned long long u64;

// MUFU exp2 (guaranteed EX2.APPROX)
__device__ __forceinline__ float ex2f(float x) {
    float y; asm("ex2.approx.f32 %0, %1;" : "=f"(y) : "f"(x)); return y;
}

// Packed fp32x2 helpers
__device__ __forceinline__ u64 ffma2(u64 a, u64 b, u64 c) {
    u64 d;
    asm("fma.rn.f32x2 %0, %1, %2, %3;" : "=l"(d) : "l"(a), "l"(b), "l"(c));
    return d;
}
__device__ __forceinline__ u64 fmul2(u64 a, u64 b) {
    u64 d;
    asm("mul.rn.f32x2 %0, %1, %2;" : "=l"(d) : "l"(a), "l"(b));
    return d;
}
__device__ __forceinline__ u64 fadd2(u64 a, u64 b) {
    u64 d;
    asm("add.rn.f32x2 %0, %1, %2;" : "=l"(d) : "l"(a), "l"(b));
    return d;
}
__device__ __forceinline__ u64 pack2(float lo, float hi) {
    u64 d; asm("mov.b64 %0, {%1, %2};" : "=l"(d) : "f"(lo), "f"(hi)); return d;
}
__device__ __forceinline__ float2 unpack2(u64 v) {
    float lo, hi; asm("mov.b64 {%0, %1}, %2;" : "=f"(lo), "=f"(hi) : "l"(v));
    return make_float2(lo, hi);
}

// Packed exp2 on the FMA pipe (degree-5 poly, rel err ~2e-6).
__device__ __forceinline__ u64 exp2_poly2(float y0, float y1) {
    y0 = fmaxf(y0, -120.f);
    y1 = fmaxf(y1, -120.f);
    u64 y = pack2(y0, y1);
    const u64 C  = pack2(12582912.f, 12582912.f);    // 1.5*2^23
    const u64 nC = pack2(-12582912.f, -12582912.f);
    const u64 n1 = pack2(-1.f, -1.f);
    u64 z  = fadd2(y, C);
    u64 iz = fadd2(z, nC);
    u64 f  = ffma2(iz, n1, y);
    u64 p  = pack2(0.00133335581f, 0.00133335581f);
    p = ffma2(p, f, pack2(0.00961812911f, 0.00961812911f));
    p = ffma2(p, f, pack2(0.05550410866f, 0.05550410866f));
    p = ffma2(p, f, pack2(0.24022650696f, 0.24022650696f));
    p = ffma2(p, f, pack2(0.69314718056f, 0.69314718056f));
    p = ffma2(p, f, pack2(1.f, 1.f));
    uint32_t zlo, zhi;
    asm("mov.b64 {%0,%1}, %2;" : "=r"(zlo), "=r"(zhi) : "l"(z));
    uint32_t slo = zlo * 8388608u + 0x3F800000u;
    uint32_t shi = zhi * 8388608u + 0x3F800000u;
    u64 s; asm("mov.b64 %0, {%1,%2};" : "=l"(s) : "r"(slo), "r"(shi));
    return fmul2(p, s);
}

// cp.async helpers
__device__ __forceinline__ void cp_async16(uint32_t s, const void* g) {
    asm volatile("cp.async.cg.shared.global [%0], [%1], 16;" :: "r"(s), "l"(g));
}
__device__ __forceinline__ void cp_commit() {
    asm volatile("cp.async.commit_group;" ::: "memory");
}
__device__ __forceinline__ void cp_wait0() {
    asm volatile("cp.async.wait_group 0;" ::: "memory");
}

// Scratch (device globals). All entries fully rewritten each call.
__device__ float g_ctx_part[(size_t)BH * CH * MFEAT * DHEAD]; // 67 MB
__device__ float g_ksum_part[BH * CH * MFEAT];
__device__ float g_lmax[BH * CH * 2];     // log2-domain
__device__ float g_scale[BH * CH * 2];
__device__ float g_vsum[BH * DHEAD];
__device__ float g_ctx[(size_t)BH * MFEAT * DHEAD];           // 4 MB
__device__ float g_ksum[BH * MFEAT];

// ---------------------------------------------------------------------------
// k12: fused K-features + partial ctx/ksum (unchanged, passing).
// ---------------------------------------------------------------------------
#define K12_SMEM 84480

__global__ __launch_bounds__(256, 2) void k12_ctx(const float* __restrict__ K,
                                                  const float* __restrict__ V,
                                                  const float* __restrict__ P) {
    extern __shared__ __align__(16) char smraw[];
    float* Pt  = (float*)smraw;                    // [64][132]
    float* Ks  = (float*)(smraw + 33792);          // [2][32][68]
    float* Vs  = (float*)(smraw + 51200);          // [2][32][64]
    float* kps = (float*)(smraw + 67584);          // [32][132]
    __shared__ float wmax[8];

    const int bh = blockIdx.y;
    const int chunk = blockIdx.x >> 1;
    const int fh = blockIdx.x & 1;
    const int fbase = fh * 128;
    const int t = threadIdx.x;
    const int w = t >> 5, lane = t & 31;
    const int fgrp = (w & 3) * 32 + (lane & 7) * 4;
    const int egrp = (w >> 2) * 32 + (lane >> 3) * 8;

    const float* kb = K + ((size_t)bh * NSEQ + (size_t)chunk * 256) * 64;
    const float* vb = V + ((size_t)bh * NSEQ + (size_t)chunk * 256) * 64;

    uint32_t ks_s = (uint32_t)__cvta_generic_to_shared(Ks);
    uint32_t vs_s = (uint32_t)__cvta_generic_to_shared(Vs);

    {
        int c0 = t, c1 = t + 256;
        int r0 = c0 >> 4, q0 = c0 & 15, r1 = c1 >> 4, q1 = c1 & 15;
        cp_async16(ks_s + r0 * 272 + q0 * 16, kb + r0 * 64 + q0 * 4);
        cp_async16(ks_s + r1 * 272 + q1 * 16, kb + r1 * 64 + q1 * 4);
        cp_async16(vs_s + r0 * 256 + q0 * 16, vb + r0 * 64 + q0 * 4);
        cp_async16(vs_s + r1 * 256 + q1 * 16, vb + r1 * 64 + q1 * 4);
        cp_commit();
    }

    for (int idx = t; idx < 128 * 64; idx += 256) {
        int f = idx >> 6, d = idx & 63;
        Pt[d * 132 + f] = DN_L2E * P[(size_t)(fbase + f) * 64 + d];
    }

    u64 ctx2[16];
    #pragma unroll
    for (int i = 0; i < 16; i++) ctx2[i] = 0ull;
    float ks0 = 0.f, ks1 = 0.f, ks2 = 0.f, ks3 = 0.f;
    float M = -1e30f;

    for (int st = 0; st < STAGES; st++) {
        const int buf = st & 1;
        cp_wait0();
        __syncthreads();

        if (st + 1 < STAGES) {
            const float* kn = kb + (st + 1) * 32 * 64;
            const float* vn = vb + (st + 1) * 32 * 64;
            uint32_t kd = ks_s + (buf ^ 1) * 8704;
            uint32_t vd = vs_s + (buf ^ 1) * 8192;
            int c0 = t, c1 = t + 256;
            int r0 = c0 >> 4, q0 = c0 & 15, r1 = c1 >> 4, q1 = c1 & 15;
            cp_async16(kd + r0 * 272 + q0 * 16, kn + r0 * 64 + q0 * 4);
            cp_async16(kd + r1 * 272 + q1 * 16, kn + r1 * 64 + q1 * 4);
            cp_async16(vd + r0 * 256 + q0 * 16, vn + r0 * 64 + q0 * 4);
            cp_async16(vd + r1 * 256 + q1 * 16, vn + r1 * 64 + q1 * 4);
            cp_commit();
        }

        const float* ksb = Ks + buf * 2176;
        const float* vsb = Vs + buf * 2048;

        float diag_r[4];
        #pragma unroll
        for (int i = 0; i < 4; i++) {
            const float* kr = ksb + (w * 4 + i) * 68;
            float2 v2 = *(const float2*)(kr + 2 * lane);
            float ss = v2.x * v2.x + v2.y * v2.y;
            #pragma unroll
            for (int o = 16; o; o >>= 1) ss += __shfl_xor_sync(0xffffffffu, ss, o);
            diag_r[i] = HDN2_L2E * ss;
        }

        u64 acc[4][2];
        #pragma unroll
        for (int i = 0; i < 4; i++) { acc[i][0] = 0ull; acc[i][1] = 0ull; }
        const float* kr0 = ksb + (w * 4 + 0) * 68;
        const float* kr1 = ksb + (w * 4 + 1) * 68;
        const float* kr2 = ksb + (w * 4 + 2) * 68;
        const float* kr3 = ksb + (w * 4 + 3) * 68;
        #pragma unroll 4
        for (int d = 0; d < 64; d += 4) {
            float4 k0 = *(const float4*)(kr0 + d);
            float4 k1 = *(const float4*)(kr1 + d);
            float4 k2 = *(const float4*)(kr2 + d);
            float4 k3 = *(const float4*)(kr3 + d);
            #pragma unroll
            for (int q = 0; q < 4; q++) {
                ulonglong2 pv = *(const ulonglong2*)(Pt + (d + q) * 132 + lane * 4);
                float kq0 = (q == 0) ? k0.x : (q == 1) ? k0.y : (q == 2) ? k0.z : k0.w;
                float kq1 = (q == 0) ? k1.x : (q == 1) ? k1.y : (q == 2) ? k1.z : k1.w;
                float kq2 = (q == 0) ? k2.x : (q == 1) ? k2.y : (q == 2) ? k2.z : k2.w;
                float kq3 = (q == 0) ? k3.x : (q == 1) ? k3.y : (q == 2) ? k3.z : k3.w;
                u64 b0 = pack2(kq0, kq0), b1 = pack2(kq1, kq1);
                u64 b2 = pack2(kq2, kq2), b3 = pack2(kq3, kq3);
                acc[0][0] = ffma2(b0, pv.x, acc[0][0]); acc[0][1] = ffma2(b0, pv.y, acc[0][1]);
                acc[1][0] = ffma2(b1, pv.x, acc[1][0]); acc[1][1] = ffma2(b1, pv.y, acc[1][1]);
                acc[2][0] = ffma2(b2, pv.x, acc[2][0]); acc[2][1] = ffma2(b2, pv.y, acc[2][1]);
                acc[3][0] = ffma2(b3, pv.x, acc[3][0]); acc[3][1] = ffma2(b3, pv.y, acc[3][1]);
            }
        }

        float dd[4][4];
        float mx = -1e30f;
        #pragma unroll
        for (int i = 0; i < 4; i++) {
            float2 lo = unpack2(acc[i][0]);
            float2 hi = unpack2(acc[i][1]);
            dd[i][0] = lo.x; dd[i][1] = lo.y;
            dd[i][2] = hi.x; dd[i][3] = hi.y;
            mx = fmaxf(mx, fmaxf(fmaxf(dd[i][0], dd[i][1]), fmaxf(dd[i][2], dd[i][3])));
        }
        #pragma unroll
        for (int o = 16; o; o >>= 1) mx = fmaxf(mx, __shfl_xor_sync(0xffffffffu, mx, o));
        if (lane == 0) wmax[w] = mx;
        __syncthreads();
        float smax = wmax[0];
        #pragma unroll
        for (int i = 1; i < 8; i++) smax = fmaxf(smax, wmax[i]);

        if (smax > M) {
            float sc = ex2f(M - smax);
            u64 sc2 = pack2(sc, sc);
            #pragma unroll
            for (int i = 0; i < 16; i++) ctx2[i] = fmul2(ctx2[i], sc2);
            ks0 *= sc; ks1 *= sc; ks2 *= sc; ks3 *= sc;
            M = smax;
        }

        #pragma unroll
        for (int i = 0; i < 4; i++) {
            float dmi = diag_r[i] + M;
            float k0, k1, k2v, k3v;
            if ((i & 1) == 0) {
                u64 ea = exp2_poly2(dd[i][0] - dmi, dd[i][1] - dmi);
                u64 eb = exp2_poly2(dd[i][2] - dmi, dd[i][3] - dmi);
                float2 fa = unpack2(ea), fb = unpack2(eb);
                k0 = fa.x; k1 = fa.y; k2v = fb.x; k3v = fb.y;
            } else {
                k0  = ex2f(dd[i][0] - dmi);
                k1  = ex2f(dd[i][1] - dmi);
                k2v = ex2f(dd[i][2] - dmi);
                k3v = ex2f(dd[i][3] - dmi);
            }
            ks0 += k0; ks1 += k1; ks2 += k2v; ks3 += k3v;
            *(float4*)(kps + (w * 4 + i) * 132 + lane * 4) = make_float4(k0, k1, k2v, k3v);
        }
        __syncthreads();

        #pragma unroll 4
        for (int r = 0; r < 32; r++) {
            ulonglong2 kp4 = *(const ulonglong2*)(kps + r * 132 + fgrp);
            float2 klo = unpack2(kp4.x), khi = unpack2(kp4.y);
            u64 b0 = pack2(klo.x, klo.x), b1 = pack2(klo.y, klo.y);
            u64 b2 = pack2(khi.x, khi.x), b3 = pack2(khi.y, khi.y);
            const ulonglong2* vp = (const ulonglong2*)(vsb + r * 64 + egrp);
            ulonglong2 vA = vp[0], vB = vp[1];
            ctx2[0]  = ffma2(b0, vA.x, ctx2[0]);  ctx2[1]  = ffma2(b0, vA.y, ctx2[1]);
            ctx2[2]  = ffma2(b0, vB.x, ctx2[2]);  ctx2[3]  = ffma2(b0, vB.y, ctx2[3]);
            ctx2[4]  = ffma2(b1, vA.x, ctx2[4]);  ctx2[5]  = ffma2(b1, vA.y, ctx2[5]);
            ctx2[6]  = ffma2(b1, vB.x, ctx2[6]);  ctx2[7]  = ffma2(b1, vB.y, ctx2[7]);
            ctx2[8]  = ffma2(b2, vA.x, ctx2[8]);  ctx2[9]  = ffma2(b2, vA.y, ctx2[9]);
            ctx2[10] = ffma2(b2, vB.x, ctx2[10]); ctx2[11] = ffma2(b2, vB.y, ctx2[11]);
            ctx2[12] = ffma2(b3, vA.x, ctx2[12]); ctx2[13] = ffma2(b3, vA.y, ctx2[13]);
            ctx2[14] = ffma2(b3, vB.x, ctx2[14]); ctx2[15] = ffma2(b3, vB.y, ctx2[15]);
        }
    }

    __syncthreads();

    {
        float* base = g_ctx_part + ((size_t)(bh * CH + chunk) * MFEAT) * DHEAD;
        #pragma unroll
        for (int j = 0; j < 4; j++) {
            float* op = base + (size_t)(fbase + fgrp + j) * DHEAD + egrp;
            ((ulonglong2*)op)[0] = make_ulonglong2(ctx2[j * 4 + 0], ctx2[j * 4 + 1]);
            ((ulonglong2*)op)[1] = make_ulonglong2(ctx2[j * 4 + 2], ctx2[j * 4 + 3]);
        }
    }

    *(float4*)(kps + w * 128 + lane * 4) = make_float4(ks0, ks1, ks2, ks3);
    __syncthreads();
    if (t < 128) {
        float s = 0.f;
        #pragma unroll
        for (int w2 = 0; w2 < 8; w2++) s += kps[w2 * 128 + t];
        g_ksum_part[(bh * CH + chunk) * MFEAT + fbase + t] = s;
    }
    if (t == 0) g_lmax[(bh * CH + chunk) * 2 + fh] = M;
}

// ---------------------------------------------------------------------------
// kvsum: vsum + folded kscale (unchanged).
// ---------------------------------------------------------------------------
__global__ __launch_bounds__(256) void kvsum(const float* __restrict__ V) {
    __shared__ float psum[16][64];
    const int bh = blockIdx.x, t = threadIdx.x;
    const int e4 = t & 15, rc = t >> 4;
    const float4* vb = (const float4*)V + (size_t)bh * NSEQ * 16;
    float4 acc = make_float4(0.f, 0.f, 0.f, 0.f);
    #pragma unroll 8
    for (int it = 0; it < 256; it++) {
        float4 a = vb[(size_t)(rc + 16 * it) * 16 + e4];
        acc.x += a.x; acc.y += a.y; acc.z += a.z; acc.w += a.w;
    }
    psum[rc][e4*4+0] = acc.x; psum[rc][e4*4+1] = acc.y;
    psum[rc][e4*4+2] = acc.z; psum[rc][e4*4+3] = acc.w;
    __syncthreads();
    if (t < 64) {
        float s = 0.f;
        #pragma unroll
        for (int r = 0; r < 16; r++) s += psum[r][t];
        g_vsum[bh * 64 + t] = s;
    }
    if (t < 32) {
        float lm = g_lmax[bh * 32 + t];
        float mx = lm;
        #pragma unroll
        for (int o = 16; o; o >>= 1) mx = fmaxf(mx, __shfl_xor_sync(0xffffffffu, mx, o));
        g_scale[bh * 32 + t] = ex2f(lm - mx);
    }
}

// ---------------------------------------------------------------------------
__global__ void k2_reduce() {
    const size_t NCTX = (size_t)BH * MFEAT * DHEAD;  // 1048576
    size_t idx = (size_t)blockIdx.x * 256 + threadIdx.x;
    if (idx < NCTX) {
        size_t bh = idx >> 14;
        size_t rem = idx & 16383;
        size_t feat = rem >> 6;
        size_t fh = feat >> 7;
        size_t e = idx & 63;
        float s = 0.f;
        #pragma unroll
        for (int c = 0; c < CH; c++)
            s += g_scale[bh * CH * 2 + c * 2 + fh] *
                 g_ctx_part[(((size_t)bh * CH + c) << 14) + rem];
        g_ctx[idx] = RATIO * (s + KEPS * g_vsum[(bh << 6) + e]);
    } else if (idx < NCTX + (size_t)BH * MFEAT) {
        size_t i2 = idx - NCTX;
        size_t bh = i2 >> 8, j = i2 & 255;
        size_t fh = j >> 7;
        float s = 0.f;
        #pragma unroll
        for (int c = 0; c < CH; c++)
            s += g_scale[bh * CH * 2 + c * 2 + fh] *
                 g_ksum_part[(bh * CH + c) * MFEAT + j];
        g_ksum[i2] = RATIO * (s + KEPS * (float)NSEQ);
    }
}

// ---------------------------------------------------------------------------
// k3: 512 threads (16 warps/SM), 128-row tiles, full-resident ctx.
// Row ownership everywhere: rows {rgi, rgi+32, rgi+64, rgi+96}, rgi = t>>4
// -> in-warp row pairs differ by 1 (264-stride => 8 banks mod 32, no conflict).
// smem: dds[128][264] @0 (135168) | overlay @135168:
//   phase1: qsm[128][64] (32768) @135168; Pth[64][132] (33792) @167936
//   phase2: ctx[256][64] (65536) @135168
// total 201728.
// ---------------------------------------------------------------------------
#define K3_SMEM_BYTES 201728
#define K3_T 512

__global__ __launch_bounds__(K3_T, 1) void k3_out(const float* __restrict__ Q,
                                                  const float* __restrict__ P,
                                                  float* __restrict__ O) {
    extern __shared__ __align__(16) char smraw[];
    float (*dds)[264] = (float (*)[264])smraw;             // [128][264]
    float (*qsm)[64]  = (float (*)[64])(smraw + 135168);   // [128][64], phase 1
    float* Pth        = (float*)(smraw + 167936);          // [64][132], phase 1
    float* ctxs       = (float*)(smraw + 135168);          // [256][64], phase 2
    __shared__ float ksum_s[256];
    __shared__ float diag[128];
    __shared__ float rmax[128];
    __shared__ float dinv[128];

    const int bh = blockIdx.y, tile = blockIdx.x, t = threadIdx.x;
    const int w = t >> 5, lane = t & 31;
    const int rgi = t >> 4;          // 0..31: owns rows rgi + 32*i
    const int fg  = (t & 15) * 4;    // feature/e-col base

    if (t < 256) ksum_s[t] = g_ksum[bh * MFEAT + t];

    // Load Q tile (128 x 64) + per-row diag (log2 domain).
    {
        const float4* qb = (const float4*)(Q + ((size_t)bh * NSEQ + (size_t)tile * 128) * DHEAD);
        float4* qs = (float4*)&qsm[0][0];
        #pragma unroll
        for (int kq = 0; kq < 4; kq++) {
            int i = t + K3_T * kq;         // float4 index; row = i >> 4
            float4 a = qb[i];
            qs[i] = a;
            float ss = a.x*a.x + a.y*a.y + a.z*a.z + a.w*a.w;
            #pragma unroll
            for (int o = 1; o < 16; o <<= 1) ss += __shfl_xor_sync(0xffffffffu, ss, o);
            if ((t & 15) == 0) diag[i >> 4] = HDN2_L2E * ss;
        }
    }

    // dd GEMM in two 128-feature halves; 4 rows x 16 features per thread.
    #pragma unroll 1
    for (int h = 0; h < 2; h++) {
        __syncthreads();
        for (int idx = t; idx < 128 * 64; idx += K3_T) {
            int f = idx >> 6, d = idx & 63;
            Pth[d * 132 + f] = DN_L2E * P[(size_t)(h * 128 + f) * 64 + d];
        }
        __syncthreads();

        u64 a0L[4], a0H[4], a1L[4], a1H[4];
        #pragma unroll
        for (int i = 0; i < 4; i++) { a0L[i]=0; a0H[i]=0; a1L[i]=0; a1H[i]=0; }

        #pragma unroll 2
        for (int db = 0; db < 64; db += 4) {
            float4 qv[4];
            #pragma unroll
            for (int i = 0; i < 4; i++) qv[i] = *(const float4*)&qsm[rgi + 32 * i][db];
            #pragma unroll
            for (int dq = 0; dq < 4; dq++) {
                const float* prow = Pth + (db + dq) * 132 + fg;
                ulonglong2 pv0 = *(const ulonglong2*)prow;
                ulonglong2 pv1 = *(const ulonglong2*)(prow + 64);
                #pragma unroll
                for (int i = 0; i < 4; i++) {
                    float qsv = (dq == 0) ? qv[i].x : (dq == 1) ? qv[i].y
                              : (dq == 2) ? qv[i].z : qv[i].w;
                    u64 qp = pack2(qsv, qsv);
                    a0L[i] = ffma2(qp, pv0.x, a0L[i]);
                    a0H[i] = ffma2(qp, pv0.y, a0H[i]);
                    a1L[i] = ffma2(qp, pv1.x, a1L[i]);
                    a1H[i] = ffma2(qp, pv1.y, a1H[i]);
                }
            }
        }
        #pragma unroll
        for (int i = 0; i < 4; i++) {
            int r = rgi + 32 * i;
            float2 l0 = unpack2(a0L[i]), h0 = unpack2(a0H[i]);
            float2 l1 = unpack2(a1L[i]), h1 = unpack2(a1H[i]);
            *(float4*)&dds[r][h * 128 + fg]      = make_float4(l0.x, l0.y, h0.x, h0.y);
            *(float4*)&dds[r][h * 128 + 64 + fg] = make_float4(l1.x, l1.y, h1.x, h1.y);
        }
    }
    __syncthreads();   // qsm/Pth dead after this point

    // Full ctx load (64KB), hidden under rmax/exp/dinv phases.
    const uint32_t ctx_s = (uint32_t)__cvta_generic_to_shared(ctxs);
    const float* cgb = g_ctx + (size_t)bh * MFEAT * DHEAD;
    {
        #pragma unroll
        for (int q = 0; q < 8; q++) {
            int i = t + K3_T * q;          // float4 index over 16384 floats
            cp_async16(ctx_s + i * 16, cgb + i * 4);
        }
        cp_commit();
    }

    // Per-row max (8 rows per warp, 16 warps).
    #pragma unroll
    for (int rr = 0; rr < 8; rr++) {
        int r = w * 8 + rr;
        float m = dds[r][lane];
        #pragma unroll
        for (int c = 1; c < 8; c++) m = fmaxf(m, dds[r][lane + 32 * c]);
        #pragma unroll
        for (int o = 16; o; o >>= 1) m = fmaxf(m, __shfl_xor_sync(0xffffffffu, m, o));
        if (lane == 0) rmax[r] = m;
    }
    __syncthreads();

    // q' in place: col = t&255, rows (t>>8)*64 .. +63; split 1/2 poly, 1/2 MUFU.
    {
        const int ec  = t & 255;
        const int rb2 = (t >> 8) * 64;
        #pragma unroll 4
        for (int pr = 0; pr < 32; pr++) {
            int r = rb2 + pr * 2;
            float y0 = dds[r][ec]     - (diag[r]     + rmax[r]);
            float y1 = dds[r + 1][ec] - (diag[r + 1] + rmax[r + 1]);
            float k0, k1;
            if ((pr & 1) == 0) {
                float2 ee = unpack2(exp2_poly2(y0, y1));
                k0 = ee.x; k1 = ee.y;
            } else {
                k0 = ex2f(y0); k1 = ex2f(y1);
            }
            dds[r][ec]     = RATIO * (k0 + KEPS);
            dds[r + 1][ec] = RATIO * (k1 + KEPS);
        }
    }
    __syncthreads();

    // D_inv (8 rows per warp).
    #pragma unroll
    for (int rr = 0; rr < 8; rr++) {
        int r = w * 8 + rr;
        float s = 0.f;
        #pragma unroll
        for (int c = 0; c < 8; c++)
            s = fmaf(dds[r][lane + 32 * c], ksum_s[lane + 32 * c], s);
        #pragma unroll
        for (int o = 16; o; o >>= 1) s += __shfl_xor_sync(0xffffffffu, s, o);
        if (lane == 0) dinv[r] = 1.0f / s;
    }
    cp_wait0();
    __syncthreads();   // ctx + dinv visible

    // out GEMM: rows {rgi+32i} x cols fg..fg+3; single uninterrupted j-loop.
    u64 oacc[4][2];
    #pragma unroll
    for (int i = 0; i < 4; i++) { oacc[i][0] = 0ull; oacc[i][1] = 0ull; }

    #pragma unroll 2
    for (int jb = 0; jb < 256; jb += 4) {
        float4 qv[4];
        #pragma unroll
        for (int i = 0; i < 4; i++) qv[i] = *(const float4*)&dds[rgi + 32 * i][jb];
        #pragma unroll
        for (int jj = 0; jj < 4; jj++) {
            ulonglong2 cv = *(const ulonglong2*)(ctxs + (jb + jj) * 64 + fg);
            #pragma unroll
            for (int i = 0; i < 4; i++) {
                float s = (jj == 0) ? qv[i].x : (jj == 1) ? qv[i].y
                        : (jj == 2) ? qv[i].z : qv[i].w;
                u64 p = pack2(s, s);
                oacc[i][0] = ffma2(p, cv.x, oacc[i][0]);
                oacc[i][1] = ffma2(p, cv.y, oacc[i][1]);
            }
        }
    }

    const size_t rowbase = (size_t)bh * NSEQ + (size_t)tile * 128;
    #pragma unroll
    for (int i = 0; i < 4; i++) {
        int r = rgi + 32 * i;
        float dv = dinv[r];
        u64 d2 = pack2(dv, dv);
        float* ob = O + (rowbase + r) * DHEAD + fg;
        *(ulonglong2*)ob = make_ulonglong2(fmul2(oacc[i][0], d2), fmul2(oacc[i][1], d2));
    }
}

// ---------------------------------------------------------------------------
extern "C" void kernel_launch(void* const* d_in, const int* in_sizes, int n_in,
                              void* d_out, int out_size) {
    const float* q    = (const float*)d_in[0];
    const float* k    = (const float*)d_in[1];
    const float* v    = (const float*)d_in[2];
    const float* proj = (const float*)d_in[3];
    float* out = (float*)d_out;

    cudaFuncSetAttribute(k12_ctx, cudaFuncAttributeMaxDynamicSharedMemorySize, K12_SMEM);
    cudaFuncSetAttribute(k3_out, cudaFuncAttributeMaxDynamicSharedMemorySize, K3_SMEM_BYTES);

    // Launch order keeps k3 at ncu slot 5.
    k12_ctx<<<dim3(CH * 2, BH), 256, K12_SMEM>>>(k, v, proj);
    kvsum<<<BH, 256>>>(v);
    {
        const size_t total = (size_t)BH * MFEAT * DHEAD + (size_t)BH * MFEAT;
        k2_reduce<<<(unsigned)((total + 255) / 256), 256>>>();
    }
    k3_out<<<dim3(NSEQ / 128, BH), K3_T, K3_SMEM_BYTES>>>(q, proj, out);
}